// round 13
// baseline (speedup 1.0000x reference)
#include <cuda_runtime.h>
#include <math.h>

#define H 2048
#define FOURH 8192
#define NT 256   // threads per block

// Scratch — h outputs per layer + partial gates for layers 1,2
__device__ __align__(16) float g_h[3 * H];
__device__ __align__(16) float g_pg[2 * FOURH];

__device__ __forceinline__ float sigmoidf_(float x) { return 1.0f / (1.0f + expf(-x)); }

__device__ __forceinline__ float warp_red(float v) {
    #pragma unroll
    for (int o = 16; o > 0; o >>= 1) v += __shfl_xor_sync(0xffffffffu, v, o);
    return v;
}
__device__ __forceinline__ float d4(float4 a, float4 b) {
    return a.x * b.x + a.y * b.y + a.z * b.z + a.w * b.w;
}

// Read-only vector load with 256B L2 prefetch hint (DeepGEMM idiom):
// doubles the L2 fill granule -> longer DRAM bursts per row activation.
__device__ __forceinline__ float4 ldg_pf256(const float4* p) {
    float4 v;
    asm volatile("ld.global.nc.L2::256B.v4.f32 {%0,%1,%2,%3}, [%4];"
                 : "=f"(v.x), "=f"(v.y), "=f"(v.z), "=f"(v.w) : "l"(p));
    return v;
}

// 4 dot products: rows {j, j+H, j+2H, j+3H} of W [4H x H] vs h [H].
// All 8 W loads issued back-to-back into distinct registers BEFORE any FMA.
__device__ __forceinline__ void dot4(const float* __restrict__ W, int j,
                                     const float* __restrict__ h, float s[4]) {
    const int t = threadIdx.x;
    const float4* h4 = reinterpret_cast<const float4*>(h);
    const float4* r0 = reinterpret_cast<const float4*>(W) + (size_t)(0 * H + j) * 512;
    const float4* r1 = reinterpret_cast<const float4*>(W) + (size_t)(1 * H + j) * 512;
    const float4* r2 = reinterpret_cast<const float4*>(W) + (size_t)(2 * H + j) * 512;
    const float4* r3 = reinterpret_cast<const float4*>(W) + (size_t)(3 * H + j) * 512;

    float4 a0 = ldg_pf256(r0 + t);
    float4 a1 = ldg_pf256(r1 + t);
    float4 a2 = ldg_pf256(r2 + t);
    float4 a3 = ldg_pf256(r3 + t);
    float4 b0 = ldg_pf256(r0 + t + NT);
    float4 b1 = ldg_pf256(r1 + t + NT);
    float4 b2 = ldg_pf256(r2 + t + NT);
    float4 b3 = ldg_pf256(r3 + t + NT);
    float4 hv0 = __ldg(h4 + t);
    float4 hv1 = __ldg(h4 + t + NT);

    s[0] = d4(a0, hv0) + d4(b0, hv1);
    s[1] = d4(a1, hv0) + d4(b1, hv1);
    s[2] = d4(a2, hv0) + d4(b2, hv1);
    s[3] = d4(a3, hv0) + d4(b3, hv1);
}

__device__ __forceinline__ void reduce4(float s[4], float tot[4]) {
    __shared__ float sm[NT / 32][4];
    const int lane = threadIdx.x & 31;
    const int w = threadIdx.x >> 5;
    #pragma unroll
    for (int g = 0; g < 4; g++) s[g] = warp_red(s[g]);
    if (lane == 0) {
        #pragma unroll
        for (int g = 0; g < 4; g++) sm[w][g] = s[g];
    }
    __syncthreads();
    if (threadIdx.x == 0) {
        #pragma unroll
        for (int g = 0; g < 4; g++) {
            float v = 0.0f;
            #pragma unroll
            for (int ww = 0; ww < NT / 32; ww++) v += sm[ww][g];
            tot[g] = v;
        }
    }
}

// Stage 1: [0,2048) layer0 full; [2048,4096) Whh1 partial; [4096,6144) Whh2 partial.
__global__ void __launch_bounds__(NT) k_stage1(
    const float* __restrict__ x,
    const float* __restrict__ hid,
    const float* __restrict__ cell,
    const float* __restrict__ Wih0,
    const float* __restrict__ Whh0,
    const float* __restrict__ bih0, const float* __restrict__ bhh0,
    const float* __restrict__ Whh1,
    const float* __restrict__ bih1, const float* __restrict__ bhh1,
    const float* __restrict__ Whh2,
    const float* __restrict__ bih2, const float* __restrict__ bhh2,
    const float* __restrict__ bout,
    float* __restrict__ out)
{
    const int b = blockIdx.x;
    const int layer = b >> 11;
    const int j = b & (H - 1);

    if (b == 0 && threadIdx.x == 32) out[0] = __ldg(bout);

    const float* W = (layer == 0) ? Whh0 : ((layer == 1) ? Whh1 : Whh2);
    const float* h = hid + layer * H;

    float s[4];
    dot4(W, j, h, s);
    float tot[4];
    reduce4(s, tot);

    if (threadIdx.x == 0) {
        if (layer == 0) {
            const float xv = __ldg(x);
            float gate[4];
            #pragma unroll
            for (int g = 0; g < 4; g++) {
                int r = g * H + j;
                gate[g] = tot[g] + xv * __ldg(Wih0 + r) + __ldg(bih0 + r) + __ldg(bhh0 + r);
            }
            float c2 = sigmoidf_(gate[1]) * __ldg(cell + j) + sigmoidf_(gate[0]) * tanhf(gate[2]);
            float h2 = sigmoidf_(gate[3]) * tanhf(c2);
            g_h[j] = h2;
            out[1 + j] = h2;
            out[1 + 3 * H + j] = c2;
        } else {
            const float* bi = (layer == 1) ? bih1 : bih2;
            const float* bb = (layer == 1) ? bhh1 : bhh2;
            float* pg = g_pg + (layer - 1) * FOURH;
            #pragma unroll
            for (int g = 0; g < 4; g++) {
                int r = g * H + j;
                pg[r] = tot[g] + __ldg(bi + r) + __ldg(bb + r);
            }
        }
    }
}

// Finish layer (1 or 2): gates = pg + Wih * h_prev, then epilogue.
// Layer 2 also accumulates y = sum h2[j]*Wout[j] into out[0] (seeded with bout).
__global__ void __launch_bounds__(NT) k_finish(
    const float* __restrict__ Wih,
    const float* __restrict__ cell,
    const float* __restrict__ Wout,
    int layer,
    float* __restrict__ out)
{
    const int j = blockIdx.x;
    const float* hin = g_h + (layer - 1) * H;

    float s[4];
    dot4(Wih, j, hin, s);
    float tot[4];
    reduce4(s, tot);

    if (threadIdx.x == 0) {
        const float* pg = g_pg + (layer - 1) * FOURH;
        float gate[4];
        #pragma unroll
        for (int g = 0; g < 4; g++) gate[g] = tot[g] + pg[g * H + j];
        float c2 = sigmoidf_(gate[1]) * __ldg(cell + layer * H + j)
                 + sigmoidf_(gate[0]) * tanhf(gate[2]);
        float h2 = sigmoidf_(gate[3]) * tanhf(c2);
        if (layer == 1) g_h[H + j] = h2;
        out[1 + layer * H + j] = h2;
        out[1 + 3 * H + layer * H + j] = c2;
        if (layer == 2) {
            atomicAdd(&out[0], h2 * __ldg(Wout + j));
        }
    }
}

extern "C" void kernel_launch(void* const* d_in, const int* in_sizes, int n_in,
                              void* d_out, int out_size) {
    const float* x    = (const float*)d_in[0];
    const float* hid  = (const float*)d_in[1];
    const float* cell = (const float*)d_in[2];
    const float* Wih0 = (const float*)d_in[3];
    const float* Whh0 = (const float*)d_in[4];
    const float* bih0 = (const float*)d_in[5];
    const float* bhh0 = (const float*)d_in[6];
    const float* Wih1 = (const float*)d_in[7];
    const float* Whh1 = (const float*)d_in[8];
    const float* bih1 = (const float*)d_in[9];
    const float* bhh1 = (const float*)d_in[10];
    const float* Wih2 = (const float*)d_in[11];
    const float* Whh2 = (const float*)d_in[12];
    const float* bih2 = (const float*)d_in[13];
    const float* bhh2 = (const float*)d_in[14];
    const float* Wout = (const float*)d_in[15];
    const float* bout = (const float*)d_in[16];
    float* out = (float*)d_out;

    k_stage1<<<3 * H, NT>>>(x, hid, cell, Wih0,
                            Whh0, bih0, bhh0,
                            Whh1, bih1, bhh1,
                            Whh2, bih2, bhh2, bout, out);
    k_finish<<<H, NT>>>(Wih1, cell, Wout, 1, out);
    k_finish<<<H, NT>>>(Wih2, cell, Wout, 2, out);
}

// round 14
// speedup vs baseline: 1.1098x; 1.1098x over previous
#include <cuda_runtime.h>
#include <math.h>

#define H 2048
#define FOURH 8192
#define NT 256   // threads per block

// Scratch — h outputs per layer + partial gates for layers 1,2
__device__ __align__(16) float g_h[3 * H];
__device__ __align__(16) float g_pg[2 * FOURH];

__device__ __forceinline__ float sigmoidf_(float x) { return 1.0f / (1.0f + expf(-x)); }

__device__ __forceinline__ float warp_red(float v) {
    #pragma unroll
    for (int o = 16; o > 0; o >>= 1) v += __shfl_xor_sync(0xffffffffu, v, o);
    return v;
}
__device__ __forceinline__ float d4(float4 a, float4 b) {
    return a.x * b.x + a.y * b.y + a.z * b.z + a.w * b.w;
}

// 4 dot products: rows {j, j+H, j+2H, j+3H} of W [4H x H] vs h [H].
// All 8 W loads issued back-to-back into distinct registers BEFORE any FMA,
// so the memory system sees 8 outstanding LDG.128 per thread.
__device__ __forceinline__ void dot4(const float* __restrict__ W, int j,
                                     const float* __restrict__ h, float s[4]) {
    const int t = threadIdx.x;
    const float4* h4 = reinterpret_cast<const float4*>(h);
    const float4* r0 = reinterpret_cast<const float4*>(W) + (size_t)(0 * H + j) * 512;
    const float4* r1 = reinterpret_cast<const float4*>(W) + (size_t)(1 * H + j) * 512;
    const float4* r2 = reinterpret_cast<const float4*>(W) + (size_t)(2 * H + j) * 512;
    const float4* r3 = reinterpret_cast<const float4*>(W) + (size_t)(3 * H + j) * 512;

    float4 a0 = __ldcs(r0 + t);
    float4 a1 = __ldcs(r1 + t);
    float4 a2 = __ldcs(r2 + t);
    float4 a3 = __ldcs(r3 + t);
    float4 b0 = __ldcs(r0 + t + NT);
    float4 b1 = __ldcs(r1 + t + NT);
    float4 b2 = __ldcs(r2 + t + NT);
    float4 b3 = __ldcs(r3 + t + NT);
    float4 hv0 = __ldg(h4 + t);
    float4 hv1 = __ldg(h4 + t + NT);

    s[0] = d4(a0, hv0) + d4(b0, hv1);
    s[1] = d4(a1, hv0) + d4(b1, hv1);
    s[2] = d4(a2, hv0) + d4(b2, hv1);
    s[3] = d4(a3, hv0) + d4(b3, hv1);
}

__device__ __forceinline__ void reduce4(float s[4], float tot[4]) {
    __shared__ float sm[NT / 32][4];
    const int lane = threadIdx.x & 31;
    const int w = threadIdx.x >> 5;
    #pragma unroll
    for (int g = 0; g < 4; g++) s[g] = warp_red(s[g]);
    if (lane == 0) {
        #pragma unroll
        for (int g = 0; g < 4; g++) sm[w][g] = s[g];
    }
    __syncthreads();
    if (threadIdx.x == 0) {
        #pragma unroll
        for (int g = 0; g < 4; g++) {
            float v = 0.0f;
            #pragma unroll
            for (int ww = 0; ww < NT / 32; ww++) v += sm[ww][g];
            tot[g] = v;
        }
    }
}

// Stage 1: [0,2048) layer0 full; [2048,4096) Whh1 partial; [4096,6144) Whh2 partial.
__global__ void __launch_bounds__(NT) k_stage1(
    const float* __restrict__ x,
    const float* __restrict__ hid,
    const float* __restrict__ cell,
    const float* __restrict__ Wih0,
    const float* __restrict__ Whh0,
    const float* __restrict__ bih0, const float* __restrict__ bhh0,
    const float* __restrict__ Whh1,
    const float* __restrict__ bih1, const float* __restrict__ bhh1,
    const float* __restrict__ Whh2,
    const float* __restrict__ bih2, const float* __restrict__ bhh2,
    const float* __restrict__ bout,
    float* __restrict__ out)
{
    const int b = blockIdx.x;
    const int layer = b >> 11;
    const int j = b & (H - 1);

    if (b == 0 && threadIdx.x == 32) out[0] = bout[0];

    const float* W = (layer == 0) ? Whh0 : ((layer == 1) ? Whh1 : Whh2);
    const float* h = hid + layer * H;

    float s[4];
    dot4(W, j, h, s);
    float tot[4];
    reduce4(s, tot);

    if (threadIdx.x == 0) {
        if (layer == 0) {
            const float xv = x[0];
            float gate[4];
            #pragma unroll
            for (int g = 0; g < 4; g++) {
                int r = g * H + j;
                gate[g] = tot[g] + xv * Wih0[r] + bih0[r] + bhh0[r];
            }
            float c2 = sigmoidf_(gate[1]) * cell[j] + sigmoidf_(gate[0]) * tanhf(gate[2]);
            float h2 = sigmoidf_(gate[3]) * tanhf(c2);
            g_h[j] = h2;
            out[1 + j] = h2;
            out[1 + 3 * H + j] = c2;
        } else {
            const float* bi = (layer == 1) ? bih1 : bih2;
            const float* bb = (layer == 1) ? bhh1 : bhh2;
            float* pg = g_pg + (layer - 1) * FOURH;
            #pragma unroll
            for (int g = 0; g < 4; g++) {
                int r = g * H + j;
                pg[r] = tot[g] + bi[r] + bb[r];
            }
        }
    }
}

// Finish layer (1 or 2): gates = pg + Wih * h_prev, then epilogue.
// Layer 2 also accumulates y = sum h2[j]*Wout[j] into out[0] (seeded with bout).
__global__ void __launch_bounds__(NT) k_finish(
    const float* __restrict__ Wih,
    const float* __restrict__ cell,
    const float* __restrict__ Wout,
    int layer,
    float* __restrict__ out)
{
    const int j = blockIdx.x;
    const float* hin = g_h + (layer - 1) * H;

    float s[4];
    dot4(Wih, j, hin, s);
    float tot[4];
    reduce4(s, tot);

    if (threadIdx.x == 0) {
        const float* pg = g_pg + (layer - 1) * FOURH;
        float gate[4];
        #pragma unroll
        for (int g = 0; g < 4; g++) gate[g] = tot[g] + pg[g * H + j];
        float c2 = sigmoidf_(gate[1]) * cell[layer * H + j] + sigmoidf_(gate[0]) * tanhf(gate[2]);
        float h2 = sigmoidf_(gate[3]) * tanhf(c2);
        g_h[layer * H + j] = h2;
        out[1 + layer * H + j] = h2;
        out[1 + 3 * H + layer * H + j] = c2;
        if (layer == 2) {
            atomicAdd(&out[0], h2 * __ldg(&Wout[j]));
        }
    }
}

extern "C" void kernel_launch(void* const* d_in, const int* in_sizes, int n_in,
                              void* d_out, int out_size) {
    const float* x    = (const float*)d_in[0];
    const float* hid  = (const float*)d_in[1];
    const float* cell = (const float*)d_in[2];
    const float* Wih0 = (const float*)d_in[3];
    const float* Whh0 = (const float*)d_in[4];
    const float* bih0 = (const float*)d_in[5];
    const float* bhh0 = (const float*)d_in[6];
    const float* Wih1 = (const float*)d_in[7];
    const float* Whh1 = (const float*)d_in[8];
    const float* bih1 = (const float*)d_in[9];
    const float* bhh1 = (const float*)d_in[10];
    const float* Wih2 = (const float*)d_in[11];
    const float* Whh2 = (const float*)d_in[12];
    const float* bih2 = (const float*)d_in[13];
    const float* bhh2 = (const float*)d_in[14];
    const float* Wout = (const float*)d_in[15];
    const float* bout = (const float*)d_in[16];
    float* out = (float*)d_out;

    k_stage1<<<3 * H, NT>>>(x, hid, cell, Wih0,
                            Whh0, bih0, bhh0,
                            Whh1, bih1, bhh1,
                            Whh2, bih2, bhh2, bout, out);
    k_finish<<<H, NT>>>(Wih1, cell, Wout, 1, out);
    k_finish<<<H, NT>>>(Wih2, cell, Wout, 2, out);
}

// round 15
// speedup vs baseline: 1.1352x; 1.0229x over previous
#include <cuda_runtime.h>
#include <math.h>

#define H 2048
#define FOURH 8192
#define NT 256   // threads per block

// Scratch — h outputs (layers 0,1) + partial gates for layers 1,2
__device__ __align__(16) float g_h[2 * H];
__device__ __align__(16) float g_pg[2 * FOURH];

__device__ __forceinline__ float sigmoidf_(float x) { return 1.0f / (1.0f + expf(-x)); }

__device__ __forceinline__ float warp_red(float v) {
    #pragma unroll
    for (int o = 16; o > 0; o >>= 1) v += __shfl_xor_sync(0xffffffffu, v, o);
    return v;
}
__device__ __forceinline__ float d4(float4 a, float4 b) {
    return a.x * b.x + a.y * b.y + a.z * b.z + a.w * b.w;
}

// 4 dot products: rows {j, j+H, j+2H, j+3H} of W [4H x H] vs h [H].
// All 8 W loads issued back-to-back into distinct registers BEFORE any FMA.
__device__ __forceinline__ void dot4(const float* __restrict__ W, int j,
                                     const float* __restrict__ h, float s[4]) {
    const int t = threadIdx.x;
    const float4* h4 = reinterpret_cast<const float4*>(h);
    const float4* r0 = reinterpret_cast<const float4*>(W) + (size_t)(0 * H + j) * 512;
    const float4* r1 = reinterpret_cast<const float4*>(W) + (size_t)(1 * H + j) * 512;
    const float4* r2 = reinterpret_cast<const float4*>(W) + (size_t)(2 * H + j) * 512;
    const float4* r3 = reinterpret_cast<const float4*>(W) + (size_t)(3 * H + j) * 512;

    float4 a0 = __ldcs(r0 + t);
    float4 a1 = __ldcs(r1 + t);
    float4 a2 = __ldcs(r2 + t);
    float4 a3 = __ldcs(r3 + t);
    float4 b0 = __ldcs(r0 + t + NT);
    float4 b1 = __ldcs(r1 + t + NT);
    float4 b2 = __ldcs(r2 + t + NT);
    float4 b3 = __ldcs(r3 + t + NT);
    float4 hv0 = __ldg(h4 + t);
    float4 hv1 = __ldg(h4 + t + NT);

    s[0] = d4(a0, hv0) + d4(b0, hv1);
    s[1] = d4(a1, hv0) + d4(b1, hv1);
    s[2] = d4(a2, hv0) + d4(b2, hv1);
    s[3] = d4(a3, hv0) + d4(b3, hv1);
}

__device__ __forceinline__ void reduce4(float s[4], float tot[4]) {
    __shared__ float sm[NT / 32][4];
    const int lane = threadIdx.x & 31;
    const int w = threadIdx.x >> 5;
    #pragma unroll
    for (int g = 0; g < 4; g++) s[g] = warp_red(s[g]);
    if (lane == 0) {
        #pragma unroll
        for (int g = 0; g < 4; g++) sm[w][g] = s[g];
    }
    __syncthreads();
    if (threadIdx.x == 0) {
        #pragma unroll
        for (int g = 0; g < 4; g++) {
            float v = 0.0f;
            #pragma unroll
            for (int ww = 0; ww < NT / 32; ww++) v += sm[ww][g];
            tot[g] = v;
        }
    }
}

// K1 (4096 blocks): [0,2048) layer0 full epilogue; [2048,4096) Whh1 partial.
__global__ void __launch_bounds__(NT) k1(
    const float* __restrict__ x,
    const float* __restrict__ hid,
    const float* __restrict__ cell,
    const float* __restrict__ Wih0,
    const float* __restrict__ Whh0,
    const float* __restrict__ bih0, const float* __restrict__ bhh0,
    const float* __restrict__ Whh1,
    const float* __restrict__ bih1, const float* __restrict__ bhh1,
    const float* __restrict__ bout,
    float* __restrict__ out)
{
    const int b = blockIdx.x;
    const int layer = b >> 11;          // 0 or 1
    const int j = b & (H - 1);

    if (b == 0 && threadIdx.x == 32) out[0] = bout[0];

    const float* W = (layer == 0) ? Whh0 : Whh1;
    const float* h = hid + layer * H;

    float s[4];
    dot4(W, j, h, s);
    float tot[4];
    reduce4(s, tot);

    if (threadIdx.x == 0) {
        if (layer == 0) {
            const float xv = x[0];
            float gate[4];
            #pragma unroll
            for (int g = 0; g < 4; g++) {
                int r = g * H + j;
                gate[g] = tot[g] + xv * Wih0[r] + bih0[r] + bhh0[r];
            }
            float c2 = sigmoidf_(gate[1]) * cell[j] + sigmoidf_(gate[0]) * tanhf(gate[2]);
            float h2 = sigmoidf_(gate[3]) * tanhf(c2);
            g_h[j] = h2;
            out[1 + j] = h2;
            out[1 + 3 * H + j] = c2;
        } else {
            #pragma unroll
            for (int g = 0; g < 4; g++) {
                int r = g * H + j;
                g_pg[r] = tot[g] + bih1[r] + bhh1[r];
            }
        }
    }
}

// K2 (4096 blocks, interleaved): even b -> finish layer 1 (Wih1 . h0 + pg0);
// odd b -> Whh2 partial (independent of layer-1 results; inputs all ready).
__global__ void __launch_bounds__(NT) k2(
    const float* __restrict__ hid,
    const float* __restrict__ cell,
    const float* __restrict__ Wih1,
    const float* __restrict__ Whh2,
    const float* __restrict__ bih2, const float* __restrict__ bhh2,
    float* __restrict__ out)
{
    const int b = blockIdx.x;
    const int grp = b & 1;
    const int j = b >> 1;

    if (grp == 0) {
        // finish layer 1
        float s[4];
        dot4(Wih1, j, g_h, s);
        float tot[4];
        reduce4(s, tot);
        if (threadIdx.x == 0) {
            float gate[4];
            #pragma unroll
            for (int g = 0; g < 4; g++) gate[g] = tot[g] + g_pg[g * H + j];
            float c2 = sigmoidf_(gate[1]) * cell[H + j] + sigmoidf_(gate[0]) * tanhf(gate[2]);
            float h2 = sigmoidf_(gate[3]) * tanhf(c2);
            g_h[H + j] = h2;
            out[1 + H + j] = h2;
            out[1 + 4 * H + j] = c2;
        }
    } else {
        // Whh2 partial gates
        float s[4];
        dot4(Whh2, j, hid + 2 * H, s);
        float tot[4];
        reduce4(s, tot);
        if (threadIdx.x == 0) {
            #pragma unroll
            for (int g = 0; g < 4; g++) {
                int r = g * H + j;
                g_pg[FOURH + r] = tot[g] + bih2[r] + bhh2[r];
            }
        }
    }
}

// K3 (2048 blocks): finish layer 2 + output projection into out[0].
__global__ void __launch_bounds__(NT) k3(
    const float* __restrict__ Wih2,
    const float* __restrict__ cell,
    const float* __restrict__ Wout,
    float* __restrict__ out)
{
    const int j = blockIdx.x;

    float s[4];
    dot4(Wih2, j, g_h + H, s);
    float tot[4];
    reduce4(s, tot);

    if (threadIdx.x == 0) {
        float gate[4];
        #pragma unroll
        for (int g = 0; g < 4; g++) gate[g] = tot[g] + g_pg[FOURH + g * H + j];
        float c2 = sigmoidf_(gate[1]) * cell[2 * H + j] + sigmoidf_(gate[0]) * tanhf(gate[2]);
        float h2 = sigmoidf_(gate[3]) * tanhf(c2);
        out[1 + 2 * H + j] = h2;
        out[1 + 5 * H + j] = c2;
        atomicAdd(&out[0], h2 * __ldg(&Wout[j]));
    }
}

extern "C" void kernel_launch(void* const* d_in, const int* in_sizes, int n_in,
                              void* d_out, int out_size) {
    const float* x    = (const float*)d_in[0];
    const float* hid  = (const float*)d_in[1];
    const float* cell = (const float*)d_in[2];
    const float* Wih0 = (const float*)d_in[3];
    const float* Whh0 = (const float*)d_in[4];
    const float* bih0 = (const float*)d_in[5];
    const float* bhh0 = (const float*)d_in[6];
    const float* Wih1 = (const float*)d_in[7];
    const float* Whh1 = (const float*)d_in[8];
    const float* bih1 = (const float*)d_in[9];
    const float* bhh1 = (const float*)d_in[10];
    const float* Wih2 = (const float*)d_in[11];
    const float* Whh2 = (const float*)d_in[12];
    const float* bih2 = (const float*)d_in[13];
    const float* bhh2 = (const float*)d_in[14];
    const float* Wout = (const float*)d_in[15];
    const float* bout = (const float*)d_in[16];
    float* out = (float*)d_out;

    k1<<<2 * H, NT>>>(x, hid, cell, Wih0,
                      Whh0, bih0, bhh0,
                      Whh1, bih1, bhh1, bout, out);
    k2<<<2 * H, NT>>>(hid, cell, Wih1, Whh2, bih2, bhh2, out);
    k3<<<H, NT>>>(Wih2, cell, Wout, out);
}